// round 16
// baseline (speedup 1.0000x reference)
#include <cuda_runtime.h>
#include <math.h>

#define MM      8
#define AA      48
#define NSPEC   4
#define NPAIRCH 10
#define NSHFR   16
#define RADDIM  (NSPEC * NSHFR)            /* 64  */
#define ANGDIM  (NPAIRCH * 32)             /* 320 */
#define OUTDIM  (RADDIM + ANGDIM)          /* 384 */
#define RCR_F   5.2f
#define RCA_F   3.5f
#define PI_F    3.14159265358979323846f
#define NT      384
#define NWARPS  (NT / 32)                  /* 12 */
#define MAXPAIR ((AA * (AA - 1)) / 2)      /* 1128 */
#define FULLM   0xffffffffu

__global__ __launch_bounds__(NT, 1) void aev_kernel(
    const float* __restrict__ coords,   // (M, A, 3)
    const float* __restrict__ EtaR,     // (1,)
    const float* __restrict__ ShfR,     // (16,)
    const float* __restrict__ EtaA,     // (1,)
    const float* __restrict__ Zeta,     // (1,)
    const float* __restrict__ ShfA,     // (4,)
    const float* __restrict__ ShfZ,     // (8,)
    const int*   __restrict__ species,  // (M, A)
    const int*   __restrict__ triu,     // (4, 4)
    float*       __restrict__ out)      // (M, A, 384)
{
    __shared__ float  sdd[AA];     // d (all j)
    __shared__ float  spre[AA];    // 0.25*fc_R (0 if invalid/out-of-range)
    __shared__ int    ssp[AA];     // species per j
    __shared__ float4 nA[AA];      // angular nbr: ux,uy,uz,d  (two segments)
    __shared__ float2 nB[AA];      // angular nbr: fc_A, species(bits)
    __shared__ int    cnt0, cnt1;  // per-warp-segment neighbor counts
    __shared__ float4 pairdata[MAXPAIR];        // {cos, sin, davg, 2fcfc}
    __shared__ unsigned char pairp[MAXPAIR];    // channel 0..9
    __shared__ int    s_triu[NSPEC * NSPEC];
    __shared__ float  rad[RADDIM];
    __shared__ float  wang[NWARPS][ANGDIM];     // warp-private angular slices

    const int mi   = blockIdx.x;        // env = (m, i)
    const int m    = mi / AA;
    const int i    = mi % AA;
    const int tid  = threadIdx.x;
    const int wid  = tid >> 5;
    const int lane = tid & 31;

    // ---- scalar parameters (L1-cached after first block) ----
    const float etaR   = __ldg(EtaR);
    const float etaA   = __ldg(EtaA);
    const float zeta   = __ldg(Zeta);
    const float shfr_r = __ldg(&ShfR[lane & 15]);
    const float sha    = __ldg(&ShfA[lane >> 3]);
    const float shz    = __ldg(&ShfZ[lane & 7]);
    const float cz = 0.5f * __cosf(shz), sz = 0.5f * __sinf(shz);
    const bool  z32 = (zeta == 32.0f);

    // ---- merged phase 1+2: direct loads, distances, ballot compaction ----
    if (tid < NSPEC * NSPEC) s_triu[tid] = triu[tid];
    if (tid < RADDIM) rad[tid] = 0.0f;
    #pragma unroll
    for (int t = tid; t < NWARPS * ANGDIM; t += NT)
        ((float*)wang)[t] = 0.0f;

    if (wid < 2) {                        // warps 0,1 cover j = tid (0..63)
        const int  j   = tid;
        const bool has = (j < AA);

        // center atom: broadcast loads (same address across threads -> L1 hit)
        const float aix = __ldg(&coords[(m * AA + i) * 3 + 0]);
        const float aiy = __ldg(&coords[(m * AA + i) * 3 + 1]);
        const float aiz = __ldg(&coords[(m * AA + i) * 3 + 2]);
        const int   spi = __ldg(&species[m * AA + i]);

        float dx = 0.f, dy = 0.f, dz = 0.f;
        int   spj = -1;
        if (has) {
            dx  = __ldg(&coords[(m * AA + j) * 3 + 0]) - aix;
            dy  = __ldg(&coords[(m * AA + j) * 3 + 1]) - aiy;
            dz  = __ldg(&coords[(m * AA + j) * 3 + 2]) - aiz;
            spj = __ldg(&species[m * AA + j]);
        }
        float d2 = dx * dx + dy * dy + dz * dz;
        d2 = (d2 > 0.0f) ? d2 : 1.0f;
        float rinv = rsqrtf(d2);
        float d    = d2 * rinv;           // sqrt(d2) without serial sqrt+div

        bool pvb = has && (spi >= 0) && (spj >= 0) && (j != i);
        float pr = 0.0f;
        if (pvb && d <= RCR_F)
            pr = 0.25f * (0.5f * __cosf(d * (PI_F / RCR_F)) + 0.5f);
        if (has) {
            sdd[j]  = d;
            spre[j] = pr;
            ssp[j]  = spj;
        }

        // ballot compaction: warp 0 -> slots [0, c0), warp 1 -> [32, 32+c1)
        bool inA = pvb && (d <= RCA_F);
        unsigned bm = __ballot_sync(FULLM, inA);
        if (inA) {
            int idx = (wid << 5) + __popc(bm & ((1u << lane) - 1u));
            nA[idx] = make_float4(dx * rinv, dy * rinv, dz * rinv, d);
            nB[idx] = make_float2(0.5f * __cosf(d * (PI_F / RCA_F)) + 0.5f,
                                  __int_as_float(spj));
        }
        if (lane == 0) {
            if (wid == 0) cnt0 = __popc(bm);
            else          cnt1 = __popc(bm);
        }
    }
    __syncthreads();

    const int c0     = cnt0;
    const int n      = c0 + cnt1;
    const int npairs = (n * (n - 1)) >> 1;

    // ---- phase 3a: radial — 768 (j, r) items in exactly 2 passes;
    //      384 % 16 == 0 so t & 15 == lane & 15 matches shfr_r ----
    #pragma unroll
    for (int it = 0; it < 2; it++) {
        int t = tid + it * NT;
        int   j  = t >> 4;
        float pr = spre[j];
        if (pr != 0.0f) {
            float u = sdd[j] - shfr_r;
            atomicAdd(&rad[ssp[j] * NSHFR + (lane & 15)],
                      pr * __expf(-etaR * u * u));
        }
    }

    // ---- phase 3b: pair precompute — thread-per-pair, closed-form decode ----
    for (int t = tid; t < npairs; t += NT) {
        float tn = 2.0f * (float)n - 1.0f;
        int jj = (int)(0.5f * (tn - sqrtf(tn * tn - 8.0f * (float)t)));
        jj = max(0, min(jj, n - 2));
        int start = (jj * (2 * n - jj - 1)) >> 1;
        if (t < start) {
            jj--; start = (jj * (2 * n - jj - 1)) >> 1;
        } else if (t >= start + n - 1 - jj) {
            start += n - 1 - jj; jj++;
        }
        int kk = jj + 1 + (t - start);

        // logical -> physical (segment 1 lives at offset 32)
        int jp = (jj < c0) ? jj : jj - c0 + 32;
        int kp = (kk < c0) ? kk : kk - c0 + 32;

        float4 aj = nA[jp];
        float4 ak = nA[kp];
        float2 bj = nB[jp];
        float2 bk = nB[kp];
        float c = 0.95f * (aj.x * ak.x + aj.y * ak.y + aj.z * ak.z);
        c = fminf(0.99f, fmaxf(-0.99f, c));
        float4 pd;
        pd.x = c;
        pd.y = sqrtf(1.0f - c * c);            // sin(arccos(c)) >= 0
        pd.z = 0.5f * (aj.w + ak.w);           // davg
        pd.w = 2.0f * bj.x * bk.x;             // 2*fcj*fck
        pairdata[t] = pd;
        pairp[t] = (unsigned char)
            s_triu[__float_as_int(bj.y) * NSPEC + __float_as_int(bk.y)];
    }
    __syncthreads();

    // ---- phase 4: radial write (overlaps) + angular consumer, private RMW ----
    if (tid < RADDIM) out[mi * OUTDIM + tid] = rad[tid];

    {
        float* wslice = wang[wid];
        #pragma unroll 2
        for (int t = wid; t < npairs; t += NWARPS) {
            float4 pd = pairdata[t];           // LDS.128 broadcast
            int    p  = pairp[t];              // LDS.U8 broadcast
            // cos(theta - ShfZ) = c*cosZ + sin(theta)*sinZ
            float base = 0.5f + pd.x * cz + pd.y * sz;
            float f1;
            if (z32) {
                float b2 = base * base;
                float b4 = b2 * b2;
                float b8 = b4 * b4;
                float b16 = b8 * b8;
                f1 = b16 * b16;
            } else {
                f1 = __powf(base, zeta);
            }
            float uu = pd.z - sha;
            float f2 = __expf(-etaA * uu * uu);
            wslice[p * 32 + lane] += f1 * f2 * pd.w;   // private: no atomic
        }
    }
    __syncthreads();

    // ---- phase 5: fold 12 warp slices + write angular (single pass) ----
    if (tid < ANGDIM) {
        float v = 0.0f;
        #pragma unroll
        for (int w = 0; w < NWARPS; w++)
            v += wang[w][tid];
        out[mi * OUTDIM + RADDIM + tid] = v;
    }
}

extern "C" void kernel_launch(void* const* d_in, const int* in_sizes, int n_in,
                              void* d_out, int out_size)
{
    const float* coordsp = (const float*)d_in[0];
    const float* etaRp   = (const float*)d_in[1];
    const float* shfRp   = (const float*)d_in[2];
    const float* etaAp   = (const float*)d_in[3];
    const float* zetap   = (const float*)d_in[4];
    const float* shfAp   = (const float*)d_in[5];
    const float* shfZp   = (const float*)d_in[6];
    const int*   specp   = (const int*)d_in[7];
    const int*   triup   = (const int*)d_in[8];
    float*       outp    = (float*)d_out;

    aev_kernel<<<MM * AA, NT>>>(coordsp, etaRp, shfRp, etaAp, zetap, shfAp,
                                shfZp, specp, triup, outp);
}

// round 17
// speedup vs baseline: 1.0295x; 1.0295x over previous
#include <cuda_runtime.h>
#include <math.h>

#define MM      8
#define AA      48
#define NSPEC   4
#define NPAIRCH 10
#define NSHFR   16
#define RADDIM  (NSPEC * NSHFR)            /* 64  */
#define ANGDIM  (NPAIRCH * 32)             /* 320 */
#define OUTDIM  (RADDIM + ANGDIM)          /* 384 */
#define RCR_F   5.2f
#define RCA_F   3.5f
#define PI_F    3.14159265358979323846f
#define NT      384
#define NWARPS  (NT / 32)                  /* 12 */
#define MAXPAIR ((AA * (AA - 1)) / 2)      /* 1128 */
#define FULLM   0xffffffffu

__global__ __launch_bounds__(NT, 1) void aev_kernel(
    const float* __restrict__ coords,   // (M, A, 3)
    const float* __restrict__ EtaR,     // (1,)
    const float* __restrict__ ShfR,     // (16,)
    const float* __restrict__ EtaA,     // (1,)
    const float* __restrict__ Zeta,     // (1,)
    const float* __restrict__ ShfA,     // (4,)
    const float* __restrict__ ShfZ,     // (8,)
    const int*   __restrict__ species,  // (M, A)
    const int*   __restrict__ triu,     // (4, 4)
    float*       __restrict__ out)      // (M, A, 384)
{
    __shared__ float  sdd[AA];     // d (all j)
    __shared__ float  spre[AA];    // 0.25*fc_R (0 if invalid/out-of-range)
    __shared__ int    ssp[AA];     // species per j
    __shared__ float4 nA[AA];      // angular nbr: ux,uy,uz,d  (two segments)
    __shared__ float2 nB[AA];      // angular nbr: fc_A, species(bits)
    __shared__ int    cnt0, cnt1;  // per-warp-segment neighbor counts
    __shared__ float4 pairdata[MAXPAIR];        // {cos, sin, davg, 2fcfc}
    __shared__ unsigned char pairp[MAXPAIR];    // channel 0..9
    __shared__ int    s_triu[NSPEC * NSPEC];
    __shared__ float  rad[RADDIM];
    __shared__ float  wang[NWARPS][ANGDIM];     // warp-private angular slices

    const int mi   = blockIdx.x;        // env = (m, i)
    const int m    = mi / AA;
    const int i    = mi % AA;
    const int tid  = threadIdx.x;
    const int wid  = tid >> 5;
    const int lane = tid & 31;

    // ---- scalar parameters (L1-cached after first block) ----
    const float etaR   = __ldg(EtaR);
    const float etaA   = __ldg(EtaA);
    const float zeta   = __ldg(Zeta);
    const float shfr_r = __ldg(&ShfR[lane & 15]);
    const float sha    = __ldg(&ShfA[lane >> 3]);
    const float shz    = __ldg(&ShfZ[lane & 7]);
    const float cz = 0.5f * __cosf(shz), sz = 0.5f * __sinf(shz);
    const bool  z32 = (zeta == 32.0f);

    // ---- merged phase 1+2 ----
    // Warps 0-1 (the critical path): ONLY distances + ballot compaction.
    // Warps 2-11: all init/zeroing work in parallel.
    if (wid < 2) {                        // warps 0,1 cover j = tid (0..63)
        const int  j   = tid;
        const bool has = (j < AA);

        // center atom: broadcast loads (same address across threads -> L1 hit)
        const float aix = __ldg(&coords[(m * AA + i) * 3 + 0]);
        const float aiy = __ldg(&coords[(m * AA + i) * 3 + 1]);
        const float aiz = __ldg(&coords[(m * AA + i) * 3 + 2]);
        const int   spi = __ldg(&species[m * AA + i]);

        float dx = 0.f, dy = 0.f, dz = 0.f;
        int   spj = -1;
        if (has) {
            dx  = __ldg(&coords[(m * AA + j) * 3 + 0]) - aix;
            dy  = __ldg(&coords[(m * AA + j) * 3 + 1]) - aiy;
            dz  = __ldg(&coords[(m * AA + j) * 3 + 2]) - aiz;
            spj = __ldg(&species[m * AA + j]);
        }
        float d2 = dx * dx + dy * dy + dz * dz;
        d2 = (d2 > 0.0f) ? d2 : 1.0f;
        float rinv = rsqrtf(d2);
        float d    = d2 * rinv;           // sqrt(d2) without serial sqrt+div

        bool pvb = has && (spi >= 0) && (spj >= 0) && (j != i);
        float pr = 0.0f;
        if (pvb && d <= RCR_F)
            pr = 0.25f * (0.5f * __cosf(d * (PI_F / RCR_F)) + 0.5f);
        if (has) {
            sdd[j]  = d;
            spre[j] = pr;
            ssp[j]  = spj;
        }

        // ballot compaction: warp 0 -> slots [0, c0), warp 1 -> [32, 32+c1)
        bool inA = pvb && (d <= RCA_F);
        unsigned bm = __ballot_sync(FULLM, inA);
        if (inA) {
            int idx = (wid << 5) + __popc(bm & ((1u << lane) - 1u));
            nA[idx] = make_float4(dx * rinv, dy * rinv, dz * rinv, d);
            nB[idx] = make_float2(0.5f * __cosf(d * (PI_F / RCA_F)) + 0.5f,
                                  __int_as_float(spj));
        }
        if (lane == 0) {
            if (wid == 0) cnt0 = __popc(bm);
            else          cnt1 = __popc(bm);
        }
    } else {
        // warps 2-11: init work off the critical path
        int t = tid - 64;
        if (t < NSPEC * NSPEC) s_triu[t] = triu[t];
        else if (t < NSPEC * NSPEC + RADDIM) rad[t - NSPEC * NSPEC] = 0.0f;
        for (int q = t; q < NWARPS * ANGDIM; q += NT - 64)
            ((float*)wang)[q] = 0.0f;
    }
    __syncthreads();

    const int c0     = cnt0;
    const int n      = c0 + cnt1;
    const int npairs = (n * (n - 1)) >> 1;

    // ---- phase 3a: radial — 768 (j, r) items in exactly 2 passes;
    //      384 % 16 == 0 so t & 15 == lane & 15 matches shfr_r ----
    #pragma unroll
    for (int it = 0; it < 2; it++) {
        int t = tid + it * NT;
        int   j  = t >> 4;
        float pr = spre[j];
        if (pr != 0.0f) {
            float u = sdd[j] - shfr_r;
            atomicAdd(&rad[ssp[j] * NSHFR + (lane & 15)],
                      pr * __expf(-etaR * u * u));
        }
    }

    // ---- phase 3b: pair precompute — thread-per-pair, closed-form decode ----
    for (int t = tid; t < npairs; t += NT) {
        float tn = 2.0f * (float)n - 1.0f;
        int jj = (int)(0.5f * (tn - sqrtf(tn * tn - 8.0f * (float)t)));
        jj = max(0, min(jj, n - 2));
        int start = (jj * (2 * n - jj - 1)) >> 1;
        if (t < start) {
            jj--; start = (jj * (2 * n - jj - 1)) >> 1;
        } else if (t >= start + n - 1 - jj) {
            start += n - 1 - jj; jj++;
        }
        int kk = jj + 1 + (t - start);

        // logical -> physical (segment 1 lives at offset 32)
        int jp = (jj < c0) ? jj : jj - c0 + 32;
        int kp = (kk < c0) ? kk : kk - c0 + 32;

        float4 aj = nA[jp];
        float4 ak = nA[kp];
        float2 bj = nB[jp];
        float2 bk = nB[kp];
        float c = 0.95f * (aj.x * ak.x + aj.y * ak.y + aj.z * ak.z);
        c = fminf(0.99f, fmaxf(-0.99f, c));
        float4 pd;
        pd.x = c;
        pd.y = sqrtf(1.0f - c * c);            // sin(arccos(c)) >= 0
        pd.z = 0.5f * (aj.w + ak.w);           // davg
        pd.w = 2.0f * bj.x * bk.x;             // 2*fcj*fck
        pairdata[t] = pd;
        pairp[t] = (unsigned char)
            s_triu[__float_as_int(bj.y) * NSPEC + __float_as_int(bk.y)];
    }
    __syncthreads();

    // ---- phase 4: radial write (overlaps) + angular consumer, private RMW ----
    if (tid < RADDIM) out[mi * OUTDIM + tid] = rad[tid];

    {
        float* wslice = wang[wid];
        #pragma unroll 2
        for (int t = wid; t < npairs; t += NWARPS) {
            float4 pd = pairdata[t];           // LDS.128 broadcast
            int    p  = pairp[t];              // LDS.U8 broadcast
            // cos(theta - ShfZ) = c*cosZ + sin(theta)*sinZ
            float base = 0.5f + pd.x * cz + pd.y * sz;
            float f1;
            if (z32) {
                float b2 = base * base;
                float b4 = b2 * b2;
                float b8 = b4 * b4;
                float b16 = b8 * b8;
                f1 = b16 * b16;
            } else {
                f1 = __powf(base, zeta);
            }
            float uu = pd.z - sha;
            float f2 = __expf(-etaA * uu * uu);
            wslice[p * 32 + lane] += f1 * f2 * pd.w;   // private: no atomic
        }
    }
    __syncthreads();

    // ---- phase 5: fold 12 warp slices + write angular (single pass) ----
    if (tid < ANGDIM) {
        float v = 0.0f;
        #pragma unroll
        for (int w = 0; w < NWARPS; w++)
            v += wang[w][tid];
        out[mi * OUTDIM + RADDIM + tid] = v;
    }
}

extern "C" void kernel_launch(void* const* d_in, const int* in_sizes, int n_in,
                              void* d_out, int out_size)
{
    const float* coordsp = (const float*)d_in[0];
    const float* etaRp   = (const float*)d_in[1];
    const float* shfRp   = (const float*)d_in[2];
    const float* etaAp   = (const float*)d_in[3];
    const float* zetap   = (const float*)d_in[4];
    const float* shfAp   = (const float*)d_in[5];
    const float* shfZp   = (const float*)d_in[6];
    const int*   specp   = (const int*)d_in[7];
    const int*   triup   = (const int*)d_in[8];
    float*       outp    = (float*)d_out;

    aev_kernel<<<MM * AA, NT>>>(coordsp, etaRp, shfRp, etaAp, zetap, shfAp,
                                shfZp, specp, triup, outp);
}